// round 13
// baseline (speedup 1.0000x reference)
#include <cuda_runtime.h>
#include <cuda_fp16.h>
#include <math.h>
#include <stdint.h>

#define BB 512
#define NN 50
#define DD 768
#define D4 3072
#define FLAT (NN*DD)   // 38400

#define ROWH 40                     // halves per A smem row (80B)
#define STAGE_H (128*ROWH)

// persistent LSTM: 128 blocks, tile M128 x N96, Whh N-tile resident
#define NT 96                       // N (gate cols) per block
#define NBLK 128                    // 4 M-tiles * 32 N-tiles
#define PAD_B 776                   // halves per resident-B row
#define PRS_BH (NT*PAD_B)           // 74496 halves = 148992 B
#define A_ST_H (128*ROWH)           // 5120 halves per A stage
#define EBUF_B (128*NT*4)           // 49152 B (separate epilogue buffer)
#define PRS_SMEM (PRS_BH*2 + 3*A_ST_H*2 + EBUF_B)   // 228864 B

// ---------------- scratch (__device__ globals; no allocation allowed) ----------------
__device__ float  g_att[BB*DD];                             // per-batch EGCE text gate
__device__ __align__(16) __half s_shift16[BB*FLAT];
__device__ __align__(16) __half s_xg16[(size_t)BB*NN*D4];   // permuted gate pre-acts
__device__ __align__(16) __half s_h16a[BB*DD];
__device__ __align__(16) __half s_h16b[BB*DD];
__device__ float  s_c  [BB*DD];
__device__ __align__(16) __half s_vmam16[BB*2*DD];          // [b][vm|am]
__device__ float  s_fc [BB*DD];
__device__ __align__(16) __half s_Wih16p[(size_t)D4*DD];    // gate-interleaved rows
__device__ __align__(16) __half s_Whh16p[(size_t)D4*DD];
__device__ __align__(16) __half s_vWc16 [(size_t)DD*2*DD];  // [n][vW0|vW1+vW2]
__device__ float  s_bias_p[D4];
__device__ float  s_vbsum[DD];
__device__ int    g_cnt;
__device__ int    g_gen;

__device__ __forceinline__ float fsig(float x){
    return __fdividef(1.f, 1.f + __expf(-x));
}
__device__ __forceinline__ float ftanh(float x){
    return __fdividef(2.f, 1.f + __expf(-2.f*x)) - 1.f;
}
__device__ __forceinline__ uint32_t smem_u32(const void* p){
    uint32_t a;
    asm("{ .reg .u64 t; cvta.to.shared.u64 t, %1; cvt.u32.u64 %0, t; }"
        : "=r"(a) : "l"(p));
    return a;
}

// ---------------- prep: convert weights to fp16 (permuted), combine biases ----------
__global__ __launch_bounds__(256) void prep_kernel(
    const float* __restrict__ Wih, const float* __restrict__ Whh,
    const float* __restrict__ bih, const float* __restrict__ bhh,
    const float* __restrict__ vW,  const float* __restrict__ vb)
{
    int i = blockIdx.x*256 + threadIdx.x;
    if (i < D4*DD) {
        int p = i / DD, k = i - p*DD;
        int orig = (p & 3)*DD + (p >> 2);          // gate-interleave: p = 4*jj + gate
        s_Wih16p[i] = __float2half_rn(Wih[(size_t)orig*DD + k]);
        s_Whh16p[i] = __float2half_rn(Whh[(size_t)orig*DD + k]);
    }
    if (i < D4) {
        int orig = (i & 3)*DD + (i >> 2);
        s_bias_p[i] = bih[orig] + bhh[orig];
    }
    if (i < DD*DD) {
        int n = i / DD, k = i - n*DD;
        s_vWc16[(size_t)n*2*DD + k]      = __float2half_rn(vW[i]);
        s_vWc16[(size_t)n*2*DD + DD + k] =
            __float2half_rn(vW[DD*DD + i] + vW[2*DD*DD + i]);
    }
    if (i < DD) s_vbsum[i] = vb[i] + vb[DD+i] + vb[2*DD+i];
}

// ---------------- EGCE visual/acoustic: gated means straight from tables -----------
__global__ __launch_bounds__(256) void egce_va(
    const int* __restrict__ vids, const int* __restrict__ aids,
    const float* __restrict__ vemb, const float* __restrict__ aemb,
    const float* __restrict__ w3)
{
    int b = blockIdx.x;
    int mode = blockIdx.y;        // 0=visual(relu), 1=acoustic
    int tid = threadIdx.x;
    __shared__ int ids[NN];
    __shared__ float gap[DD], att[DD];
    if (tid < NN)
        ids[tid] = mode ? aids[b*NN+tid] : vids[b*NN+tid];
    __syncthreads();
    const float* emb = mode ? aemb : vemb;

    for (int ch = tid; ch < DD; ch += 256) {
        float s = 0.f; int base = ch*NN;
        for (int j = 0; j < NN; j++) {
            int k = base + j;
            int n = k / DD, d = k - n*DD;
            float v = emb[(size_t)ids[n]*DD + d];
            if (!mode) v = fmaxf(v, 0.f);
            s += v;
        }
        gap[ch] = s * (1.f/NN);
    }
    __syncthreads();
    float w0 = w3[0], w1 = w3[1], w2 = w3[2];
    for (int ch = tid; ch < DD; ch += 256) {
        float a = w1*gap[ch];
        if (ch > 0)    a += w0*gap[ch-1];
        if (ch < DD-1) a += w2*gap[ch+1];
        att[ch] = 1.f/(1.f+expf(-a));
    }
    __syncthreads();
    for (int d = tid; d < DD; d += 256) {
        float acc = 0.f;
        for (int n = 0; n < NN; n++) {
            float v = emb[(size_t)ids[n]*DD + d];
            if (!mode) v = fmaxf(v, 0.f);
            acc += v * att[(n*DD + d)/NN];
        }
        s_vmam16[(size_t)b*2*DD + mode*DD + d] = __float2half_rn(acc * (1.f/NN));
    }
}

// -------- fused EGCE(text) + f_cross-residual + LayerNorm -> g_att, shift16 --------
__global__ __launch_bounds__(256) void egce_ln_kernel(
    const float* __restrict__ text, const float* __restrict__ w3,
    const float* __restrict__ ln_g, const float* __restrict__ ln_b)
{
    int b = blockIdx.x, tid = threadIdx.x;
    __shared__ float gap[DD], att[DD], fcs[DD];
    const float* src = text + (size_t)b*FLAT;

    for (int ch = tid; ch < DD; ch += 256) {
        float s = 0.f; int base = ch*NN;
        #pragma unroll 5
        for (int j = 0; j < NN; j++) s += src[base+j];
        gap[ch] = s * (1.f/NN);
        fcs[ch] = s_fc[(size_t)b*DD + ch];
    }
    __syncthreads();
    float w0 = w3[0], w1 = w3[1], w2 = w3[2];
    for (int ch = tid; ch < DD; ch += 256) {
        float a = w1*gap[ch];
        if (ch > 0)    a += w0*gap[ch-1];
        if (ch < DD-1) a += w2*gap[ch+1];
        float v = 1.f/(1.f+expf(-a));
        att[ch] = v;
        g_att[(size_t)b*DD + ch] = v;
    }
    __syncthreads();

    int warp = tid >> 5, lane = tid & 31;
    __half* sout = s_shift16 + (size_t)b*FLAT;
    for (int n = warp; n < NN; n += 8) {
        int base = n*DD;
        float buf[24];
        float s = 0.f;
        #pragma unroll
        for (int i = 0; i < 24; i++) {
            int d = i*32 + lane;
            int k = base + d;
            float x = src[k] * att[(unsigned)k/(unsigned)NN];
            float v = x + fcs[d];
            buf[i] = v;
            s += v;
        }
        #pragma unroll
        for (int o = 16; o; o >>= 1) s += __shfl_xor_sync(0xFFFFFFFFu, s, o);
        float mean = s * (1.f/DD);
        float q = 0.f;
        #pragma unroll
        for (int i = 0; i < 24; i++) { float z = buf[i]-mean; q += z*z; }
        #pragma unroll
        for (int o = 16; o; o >>= 1) q += __shfl_xor_sync(0xFFFFFFFFu, q, o);
        float rstd = rsqrtf(q*(1.f/DD) + 1e-5f);
        #pragma unroll
        for (int i = 0; i < 24; i++) {
            int d = i*32 + lane;
            sout[base + d] = __float2half_rn((buf[i]-mean)*rstd*ln_g[d] + ln_b[d]);
        }
    }
}

// ================= fp16 mma mainloop (generic): 2-stage cp.async + ldmatrix ========
__device__ __forceinline__ void mainloop_f16(
    const __half* __restrict__ Ab, const __half* __restrict__ Bb, int K,
    __half* Sh, float (&acc)[4][4][4])
{
    int tid  = threadIdx.x;
    int lane = tid & 31, warp = tid >> 5;
    int wm = (warp >> 2) * 64;
    int wn = (warp & 3) * 32;
    int ntiles = K >> 5;

    int part = lane >> 3, row8 = lane & 7;
    uint32_t offA[4], offB[2];
    #pragma unroll
    for (int mi = 0; mi < 4; mi++) {
        int r = wm + mi*16 + (part & 1)*8 + row8;
        offA[mi] = (uint32_t)(r*ROWH + (part >> 1)*8) * 2;
    }
    #pragma unroll
    for (int n2 = 0; n2 < 2; n2++) {
        int r = wn + n2*16 + (part >> 1)*8 + row8;
        offB[n2] = (uint32_t)(r*ROWH + (part & 1)*8) * 2;
    }
    uint32_t sbase = smem_u32(Sh);

    auto issue = [&](int kt, int s){
        __half* As = Sh + s*2*STAGE_H;
        __half* Bs = As + STAGE_H;
        #pragma unroll
        for (int i = 0; i < 2; i++) {
            int q = tid + i*256;
            int row = q >> 2, c = q & 3;
            uint32_t da = smem_u32(As + row*ROWH + c*8);
            uint32_t db = smem_u32(Bs + row*ROWH + c*8);
            const __half* ga = Ab + (size_t)row*K + kt*32 + c*8;
            const __half* gb = Bb + (size_t)row*K + kt*32 + c*8;
            asm volatile("cp.async.cg.shared.global [%0], [%1], 16;"
                         :: "r"(da), "l"(ga) : "memory");
            asm volatile("cp.async.cg.shared.global [%0], [%1], 16;"
                         :: "r"(db), "l"(gb) : "memory");
        }
        asm volatile("cp.async.commit_group;" ::: "memory");
    };

    issue(0, 0);
    for (int kt = 0; kt < ntiles; kt++) {
        if (kt + 1 < ntiles) {
            issue(kt + 1, (kt + 1) & 1);
            asm volatile("cp.async.wait_group 1;" ::: "memory");
        } else {
            asm volatile("cp.async.wait_group 0;" ::: "memory");
        }
        __syncthreads();

        uint32_t abase = sbase + (uint32_t)(kt & 1)*2*STAGE_H*2;
        uint32_t bbase = abase + STAGE_H*2;
        #pragma unroll
        for (int kk = 0; kk < 2; kk++) {
            uint32_t koff = kk * 32;
            uint32_t a[4][4], bfr[4][2];
            #pragma unroll
            for (int mi = 0; mi < 4; mi++)
                asm volatile("ldmatrix.sync.aligned.m8n8.x4.shared.b16 "
                    "{%0,%1,%2,%3}, [%4];"
                    : "=r"(a[mi][0]), "=r"(a[mi][1]), "=r"(a[mi][2]), "=r"(a[mi][3])
                    : "r"(abase + offA[mi] + koff));
            #pragma unroll
            for (int n2 = 0; n2 < 2; n2++)
                asm volatile("ldmatrix.sync.aligned.m8n8.x4.shared.b16 "
                    "{%0,%1,%2,%3}, [%4];"
                    : "=r"(bfr[2*n2][0]), "=r"(bfr[2*n2][1]),
                      "=r"(bfr[2*n2+1][0]), "=r"(bfr[2*n2+1][1])
                    : "r"(bbase + offB[n2] + koff));
            #pragma unroll
            for (int mi = 0; mi < 4; mi++)
                #pragma unroll
                for (int ni = 0; ni < 4; ni++)
                    asm volatile(
                      "mma.sync.aligned.m16n8k16.row.col.f32.f16.f16.f32 "
                      "{%0,%1,%2,%3}, {%4,%5,%6,%7}, {%8,%9}, {%0,%1,%2,%3};"
                      : "+f"(acc[mi][ni][0]), "+f"(acc[mi][ni][1]),
                        "+f"(acc[mi][ni][2]), "+f"(acc[mi][ni][3])
                      : "r"(a[mi][0]), "r"(a[mi][1]), "r"(a[mi][2]), "r"(a[mi][3]),
                        "r"(bfr[ni][0]), "r"(bfr[ni][1]));
        }
        __syncthreads();
    }
}

// ---------------- generic GEMM: C = (A@B^T + bias)*scale; fp32 or fp16 out ---------
__global__ __launch_bounds__(256,2) void gemm_f16(
    const __half* __restrict__ A, const __half* __restrict__ Bm,
    float* __restrict__ Cf, __half* __restrict__ Ch,
    int Nn, int K, const float* __restrict__ bias, float out_scale)
{
    __shared__ __align__(16) __half Sh[4*STAGE_H];
    float acc[4][4][4];
    #pragma unroll
    for (int i=0;i<4;i++) for (int j=0;j<4;j++) for (int r=0;r<4;r++) acc[i][j][r]=0.f;

    mainloop_f16(A + (size_t)blockIdx.y*128*K, Bm + (size_t)blockIdx.x*128*K, K, Sh, acc);

    int tid = threadIdx.x;
    int warp = tid >> 5, lane = tid & 31;
    int wm = (warp >> 2) * 64, wn = (warp & 3) * 32;
    int g = lane >> 2, cq = lane & 3;
    int row0 = blockIdx.y*128 + wm;
    int col0 = blockIdx.x*128 + wn;
    #pragma unroll
    for (int mi = 0; mi < 4; mi++)
        #pragma unroll
        for (int ni = 0; ni < 4; ni++) {
            int ra = row0 + mi*16 + g;
            int rb = ra + 8;
            int n0 = col0 + ni*8 + 2*cq;
            float v0 = (acc[mi][ni][0] + bias[n0])   * out_scale;
            float v1 = (acc[mi][ni][1] + bias[n0+1]) * out_scale;
            float v2 = (acc[mi][ni][2] + bias[n0])   * out_scale;
            float v3 = (acc[mi][ni][3] + bias[n0+1]) * out_scale;
            if (Ch) {
                *(__half2*)&Ch[(size_t)ra*Nn + n0] = __floats2half2_rn(v0, v1);
                *(__half2*)&Ch[(size_t)rb*Nn + n0] = __floats2half2_rn(v2, v3);
            } else {
                Cf[(size_t)ra*Nn + n0]   = v0;
                Cf[(size_t)ra*Nn + n0+1] = v1;
                Cf[(size_t)rb*Nn + n0]   = v2;
                Cf[(size_t)rb*Nn + n0+1] = v3;
            }
        }
}

// ---------------- LSTM step 0 (h=c=0): gates directly from xg ----------------
__global__ __launch_bounds__(256) void lstm_step0_kernel(
    const float* __restrict__ text, float* __restrict__ out)
{
    int id = blockIdx.x*256 + threadIdx.x;   // < B*D
    int b = id / DD, jj = id - b*DD;
    uint2 raw = *reinterpret_cast<const uint2*>(&s_xg16[((size_t)b*NN)*D4 + 4*jj]);
    __half2 p0 = *(__half2*)&raw.x, p1 = *(__half2*)&raw.y;
    float gi = __low2float(p0), gg = __low2float(p1), go = __high2float(p1);
    float cn = fsig(gi) * ftanh(gg);
    s_c[id] = cn;
    float hn = fsig(go) * ftanh(cn);
    s_h16a[id] = __float2half_rn(hn);
    size_t oo = ((size_t)b*NN)*DD + jj;
    float ga = g_att[(size_t)b*DD + (unsigned)jj/(unsigned)NN];
    out[oo] = hn + text[oo]*ga;
}

// ---------------- persistent LSTM: 128 blocks (M128xN96), Whh resident -------------
__device__ __forceinline__ void grid_sync_all()
{
    __syncthreads();
    if (threadIdx.x == 0) {
        __threadfence();
        int gen = *(volatile int*)&g_gen;
        if (atomicAdd(&g_cnt, 1) == NBLK-1) {
            g_cnt = 0;
            __threadfence();
            *(volatile int*)&g_gen = gen + 1;
        } else {
            while (*(volatile int*)&g_gen == gen) __nanosleep(64);
        }
        __threadfence();
    }
    __syncthreads();
}

__global__ __launch_bounds__(256,1) void lstm_persistent(
    const float* __restrict__ text, float* __restrict__ out)
{
    extern __shared__ __align__(16) __half S[];
    __half* Bres = S;                          // [96][PAD_B]
    __half* Ast  = S + PRS_BH;                 // 3 A stages [128][ROWH]
    float*  ebuf = (float*)(S + PRS_BH + 3*A_ST_H);   // separate 128x96 epilogue buf
    int tid = threadIdx.x;
    int bx = blockIdx.x & 31;            // N tile (96 gate cols = 24 hidden units)
    int by = blockIdx.x >> 5;            // M tile (128 rows)

    // load resident B tile once: Whh16p rows [96*bx, +96), 768 cols
    {
        const __half* Bg = s_Whh16p + (size_t)bx*NT*DD;
        for (int i = tid; i < NT*(DD/8); i += 256) {
            int r = i / (DD/8), c8 = i - r*(DD/8);
            *reinterpret_cast<uint4*>(Bres + r*PAD_B + c8*8) =
                *reinterpret_cast<const uint4*>(Bg + (size_t)r*DD + c8*8);
        }
    }
    __syncthreads();

    int lane = tid & 31, warp = tid >> 5;
    int wm = (warp & 3) * 32;            // 4 M-splits of 32
    int wn = (warp >> 2) * 48;           // 2 N-splits of 48
    int part = lane >> 3, row8 = lane & 7;
    uint32_t offA[2], offB[3];
    #pragma unroll
    for (int mi = 0; mi < 2; mi++) {
        int r = wm + mi*16 + (part & 1)*8 + row8;
        offA[mi] = (uint32_t)(r*ROWH + (part >> 1)*8) * 2;
    }
    #pragma unroll
    for (int n4 = 0; n4 < 3; n4++) {
        int r = wn + n4*16 + (part >> 1)*8 + row8;
        offB[n4] = (uint32_t)(r*PAD_B + (part & 1)*8) * 2;
    }
    uint32_t sbA = smem_u32(Ast);
    uint32_t sbB = smem_u32(Bres);

    int g = lane >> 2, cq = lane & 3;

    for (int t = 1; t < NN; t++) {
        const __half* hin = (t & 1) ? s_h16a : s_h16b;
        __half* hout      = (t & 1) ? s_h16b : s_h16a;
        const __half* Ab = hin + (size_t)by*128*DD;

        auto issueA = [&](int kt, int s){
            #pragma unroll
            for (int i = 0; i < 2; i++) {
                int q = tid + i*256;
                int row = q >> 2, c = q & 3;
                uint32_t da = sbA + (uint32_t)(s*A_ST_H + row*ROWH + c*8)*2;
                const __half* ga = Ab + (size_t)row*DD + kt*32 + c*8;
                asm volatile("cp.async.cg.shared.global [%0], [%1], 16;"
                             :: "r"(da), "l"(ga) : "memory");
            }
            asm volatile("cp.async.commit_group;" ::: "memory");
        };

        float acc[2][6][4];
        #pragma unroll
        for (int i=0;i<2;i++) for (int j=0;j<6;j++) for (int r=0;r<4;r++) acc[i][j][r]=0.f;

        issueA(0, 0); issueA(1, 1);
        for (int kt = 0; kt < 24; kt++) {
            if (kt < 23) asm volatile("cp.async.wait_group 1;" ::: "memory");
            else         asm volatile("cp.async.wait_group 0;" ::: "memory");
            __syncthreads();                       // single sync per k-tile
            if (kt + 2 < 24) issueA(kt + 2, (kt + 2) % 3);

            uint32_t abase = sbA + (uint32_t)((kt % 3)*A_ST_H)*2;
            uint32_t bcol  = (uint32_t)(kt*32)*2;
            #pragma unroll
            for (int kk = 0; kk < 2; kk++) {
                uint32_t koff = kk * 32;
                uint32_t a[2][4], bfr[6][2];
                #pragma unroll
                for (int mi = 0; mi < 2; mi++)
                    asm volatile("ldmatrix.sync.aligned.m8n8.x4.shared.b16 "
                        "{%0,%1,%2,%3}, [%4];"
                        : "=r"(a[mi][0]), "=r"(a[mi][1]), "=r"(a[mi][2]), "=r"(a[mi][3])
                        : "r"(abase + offA[mi] + koff));
                #pragma unroll
                for (int n4 = 0; n4 < 3; n4++)
                    asm volatile("ldmatrix.sync.aligned.m8n8.x4.shared.b16 "
                        "{%0,%1,%2,%3}, [%4];"
                        : "=r"(bfr[2*n4][0]), "=r"(bfr[2*n4][1]),
                          "=r"(bfr[2*n4+1][0]), "=r"(bfr[2*n4+1][1])
                        : "r"(sbB + offB[n4] + bcol + koff));
                #pragma unroll
                for (int mi = 0; mi < 2; mi++)
                    #pragma unroll
                    for (int ni = 0; ni < 6; ni++)
                        asm volatile(
                          "mma.sync.aligned.m16n8k16.row.col.f32.f16.f16.f32 "
                          "{%0,%1,%2,%3}, {%4,%5,%6,%7}, {%8,%9}, {%0,%1,%2,%3};"
                          : "+f"(acc[mi][ni][0]), "+f"(acc[mi][ni][1]),
                            "+f"(acc[mi][ni][2]), "+f"(acc[mi][ni][3])
                          : "r"(a[mi][0]), "r"(a[mi][1]), "r"(a[mi][2]), "r"(a[mi][3]),
                            "r"(bfr[ni][0]), "r"(bfr[ni][1]));
            }
        }

        // single-shot epilogue: all warps dump acc to ebuf, one sync, fused gates
        #pragma unroll
        for (int mi = 0; mi < 2; mi++)
            #pragma unroll
            for (int ni = 0; ni < 6; ni++) {
                int c0 = wn + ni*8 + 2*cq;
                int r0 = wm + mi*16 + g;
                *reinterpret_cast<float2*>(&ebuf[r0*NT + (c0 ^ ((r0&7)<<2))]) =
                    make_float2(acc[mi][ni][0], acc[mi][ni][1]);
                int r1 = r0 + 8;
                *reinterpret_cast<float2*>(&ebuf[r1*NT + (c0 ^ ((r1&7)<<2))]) =
                    make_float2(acc[mi][ni][2], acc[mi][ni][3]);
            }
        __syncthreads();
        #pragma unroll
        for (int q = 0; q < 12; q++) {
            int idx = tid + q*256;          // < 3072 = 128 rows * 24 units
            int r = idx / 24, j = idx - r*24;
            int b = by*128 + r;
            int jjg = bx*24 + j;
            float4 acq = *reinterpret_cast<const float4*>(
                &ebuf[r*NT + ((4*j) ^ ((r&7)<<2))]);
            uint2 raw = *reinterpret_cast<const uint2*>(
                &s_xg16[((size_t)b*NN + t)*D4 + bx*NT + 4*j]);
            __half2 p0 = *(__half2*)&raw.x, p1 = *(__half2*)&raw.y;
            float gi = acq.x + __low2float(p0);
            float gf = acq.y + __high2float(p0);
            float gg = acq.z + __low2float(p1);
            float go = acq.w + __high2float(p1);
            int ci = b*DD + jjg;
            float c = s_c[ci];
            float cn = fsig(gf)*c + fsig(gi)*ftanh(gg);
            s_c[ci] = cn;
            float hn = fsig(go)*ftanh(cn);
            hout[ci] = __float2half_rn(hn);
            int flat = t*DD + jjg;
            size_t oo = (size_t)b*FLAT + flat;
            float ga = g_att[(size_t)b*DD + (unsigned)flat/(unsigned)NN];
            out[oo] = hn + text[oo]*ga;
        }
        grid_sync_all();
    }
}

// ---------------- launch ----------------
extern "C" void kernel_launch(void* const* d_in, const int* in_sizes, int n_in,
                              void* d_out, int out_size)
{
    const float* text = (const float*)d_in[0];
    const int*   vids = (const int*)  d_in[1];
    const int*   aids = (const int*)  d_in[2];
    const float* vemb = (const float*)d_in[3];
    const float* aemb = (const float*)d_in[4];
    const float* w3   = (const float*)d_in[5];
    const float* Wih  = (const float*)d_in[6];
    const float* Whh  = (const float*)d_in[7];
    const float* bih  = (const float*)d_in[8];
    const float* bhh  = (const float*)d_in[9];
    const float* lng  = (const float*)d_in[10];
    const float* lnb  = (const float*)d_in[11];
    const float* vW   = (const float*)d_in[20];   // ca_vW [3,768,768]
    const float* vb   = (const float*)d_in[21];   // ca_vb [3,768]
    float* out = (float*)d_out;

    cudaFuncSetAttribute(lstm_persistent,
        cudaFuncAttributeMaxDynamicSharedMemorySize, PRS_SMEM);

    __half *p_vmam16, *p_shift16, *p_vWc16, *p_Wih16p, *p_xg16;
    float *p_fc, *p_vbsum, *p_bias_p;
    cudaGetSymbolAddress((void**)&p_vmam16, s_vmam16);
    cudaGetSymbolAddress((void**)&p_shift16, s_shift16);
    cudaGetSymbolAddress((void**)&p_vWc16, s_vWc16);
    cudaGetSymbolAddress((void**)&p_Wih16p, s_Wih16p);
    cudaGetSymbolAddress((void**)&p_xg16, s_xg16);
    cudaGetSymbolAddress((void**)&p_fc, s_fc);
    cudaGetSymbolAddress((void**)&p_vbsum, s_vbsum);
    cudaGetSymbolAddress((void**)&p_bias_p, s_bias_p);

    prep_kernel<<<(D4*DD + 255)/256, 256>>>(Wih, Whh, bih, bhh, vW, vb);
    egce_va<<<dim3(BB, 2), 256>>>(vids, aids, vemb, aemb, w3);

    // f_cross (K=1536): fc = ([vm|am] @ [vW0|W12]^T + vbsum) * (50/3)
    gemm_f16<<<dim3(DD/128, BB/128), 256>>>(
        p_vmam16, p_vWc16, p_fc, nullptr, DD, 2*DD, p_vbsum, 50.f/3.f);

    // fused egce(text) + fusion residual + LN  (stores g_att; no g_text)
    egce_ln_kernel<<<BB, 256>>>(text, w3, lng, lnb);

    // xg (fp16) = shift @ Wih_perm^T + bias_perm   [25600, 3072]
    gemm_f16<<<dim3(D4/128, (BB*NN)/128), 256>>>(
        p_shift16, p_Wih16p, nullptr, p_xg16, D4, DD, p_bias_p, 1.f);

    // LSTM: t=0 from xg; t=1..49 inside one persistent kernel (128 blocks)
    lstm_step0_kernel<<<(BB*DD)/256, 256>>>(text, out);
    lstm_persistent<<<NBLK, 256, PRS_SMEM>>>(text, out);
}

// round 14
// speedup vs baseline: 1.1173x; 1.1173x over previous
#include <cuda_runtime.h>
#include <cuda_fp16.h>
#include <math.h>
#include <stdint.h>

#define BB 512
#define NN 50
#define DD 768
#define D4 3072
#define FLAT (NN*DD)   // 38400

#define ROWH 40                     // halves per A smem row (80B)
#define STAGE_H (128*ROWH)

// persistent LSTM: 128 blocks, tile M128 x N96, Whh N-tile resident
#define NT 96                       // N per block
#define NBLK 128                    // 4 * 32
#define GRPB 32                     // blocks per barrier group (same by)
#define PAD_B 776                   // halves per resident-B row
#define PRS_BH (NT*PAD_B)           // 74496 halves = 148992 B
#define A_ST_H (128*ROWH)           // 5120 halves per A stage
#define PRS_SMEM (PRS_BH*2 + 3*A_ST_H*2)   // 179712 B

// ---------------- scratch (__device__ globals; no allocation allowed) ----------------
__device__ float  g_text[BB*FLAT];
__device__ __align__(16) __half s_shift16[BB*FLAT];
__device__ __align__(16) __half s_xg16[(size_t)BB*NN*D4];   // permuted gate pre-acts
__device__ __align__(16) __half s_h16a[BB*DD];
__device__ __align__(16) __half s_h16b[BB*DD];
__device__ float  s_c  [BB*DD];
__device__ __align__(16) __half s_vmam16[BB*2*DD];          // [b][vm|am]
__device__ float  s_fc [BB*DD];
__device__ __align__(16) __half s_Wih16p[(size_t)D4*DD];    // gate-interleaved rows
__device__ __align__(16) __half s_Whh16p[(size_t)D4*DD];
__device__ __align__(16) __half s_vWc16 [(size_t)DD*2*DD];  // [n][vW0|vW1+vW2]
__device__ float  s_bias_p[D4];
__device__ float  s_vbsum[DD];
__device__ int    g_cnt4[4];
__device__ int    g_gen4[4];

__device__ __forceinline__ float fsig(float x){
    return __fdividef(1.f, 1.f + __expf(-x));
}
__device__ __forceinline__ float ftanh(float x){
    return __fdividef(2.f, 1.f + __expf(-2.f*x)) - 1.f;
}
__device__ __forceinline__ uint32_t smem_u32(const void* p){
    uint32_t a;
    asm("{ .reg .u64 t; cvta.to.shared.u64 t, %1; cvt.u32.u64 %0, t; }"
        : "=r"(a) : "l"(p));
    return a;
}

// ---------------- prep: convert weights to fp16 (permuted), combine biases ----------
__global__ __launch_bounds__(256) void prep_kernel(
    const float* __restrict__ Wih, const float* __restrict__ Whh,
    const float* __restrict__ bih, const float* __restrict__ bhh,
    const float* __restrict__ vW,  const float* __restrict__ vb)
{
    int i = blockIdx.x*256 + threadIdx.x;
    if (i < D4*DD) {
        int p = i / DD, k = i - p*DD;
        int orig = (p & 3)*DD + (p >> 2);          // gate-interleave: p = 4*jj + gate
        s_Wih16p[i] = __float2half_rn(Wih[(size_t)orig*DD + k]);
        s_Whh16p[i] = __float2half_rn(Whh[(size_t)orig*DD + k]);
    }
    if (i < D4) {
        int orig = (i & 3)*DD + (i >> 2);
        s_bias_p[i] = bih[orig] + bhh[orig];
    }
    if (i < DD*DD) {
        int n = i / DD, k = i - n*DD;
        s_vWc16[(size_t)n*2*DD + k]      = __float2half_rn(vW[i]);
        s_vWc16[(size_t)n*2*DD + DD + k] =
            __float2half_rn(vW[DD*DD + i] + vW[2*DD*DD + i]);
    }
    if (i < DD) s_vbsum[i] = vb[i] + vb[DD+i] + vb[2*DD+i];
    if (i < 4) { g_cnt4[i] = 0; g_gen4[i] = 0; }
}

// ---------------- EGCE visual/acoustic: gated means straight from tables -----------
__global__ __launch_bounds__(256) void egce_va(
    const int* __restrict__ vids, const int* __restrict__ aids,
    const float* __restrict__ vemb, const float* __restrict__ aemb,
    const float* __restrict__ w3)
{
    int b = blockIdx.x;
    int mode = blockIdx.y;        // 0=visual(relu), 1=acoustic
    int tid = threadIdx.x;
    __shared__ int ids[NN];
    __shared__ float gap[DD], att[DD];
    if (tid < NN)
        ids[tid] = mode ? aids[b*NN+tid] : vids[b*NN+tid];
    __syncthreads();
    const float* emb = mode ? aemb : vemb;

    for (int ch = tid; ch < DD; ch += 256) {
        float s = 0.f; int base = ch*NN;
        for (int j = 0; j < NN; j++) {
            int k = base + j;
            int n = k / DD, d = k - n*DD;
            float v = emb[(size_t)ids[n]*DD + d];
            if (!mode) v = fmaxf(v, 0.f);
            s += v;
        }
        gap[ch] = s * (1.f/NN);
    }
    __syncthreads();
    float w0 = w3[0], w1 = w3[1], w2 = w3[2];
    for (int ch = tid; ch < DD; ch += 256) {
        float a = w1*gap[ch];
        if (ch > 0)    a += w0*gap[ch-1];
        if (ch < DD-1) a += w2*gap[ch+1];
        att[ch] = 1.f/(1.f+expf(-a));
    }
    __syncthreads();
    for (int d = tid; d < DD; d += 256) {
        float acc = 0.f;
        for (int n = 0; n < NN; n++) {
            float v = emb[(size_t)ids[n]*DD + d];
            if (!mode) v = fmaxf(v, 0.f);
            acc += v * att[(n*DD + d)/NN];
        }
        s_vmam16[(size_t)b*2*DD + mode*DD + d] = __float2half_rn(acc * (1.f/NN));
    }
}

// -------- fused EGCE(text) + f_cross-residual + LayerNorm -> g_text, shift16 -------
__global__ __launch_bounds__(256) void egce_ln_kernel(
    const float* __restrict__ text, const float* __restrict__ w3,
    const float* __restrict__ ln_g, const float* __restrict__ ln_b)
{
    int b = blockIdx.x, tid = threadIdx.x;
    __shared__ float gap[DD], att[DD], fcs[DD];
    const float* src = text + (size_t)b*FLAT;

    for (int ch = tid; ch < DD; ch += 256) {
        float s = 0.f; int base = ch*NN;
        #pragma unroll 5
        for (int j = 0; j < NN; j++) s += src[base+j];
        gap[ch] = s * (1.f/NN);
        fcs[ch] = s_fc[(size_t)b*DD + ch];
    }
    __syncthreads();
    float w0 = w3[0], w1 = w3[1], w2 = w3[2];
    for (int ch = tid; ch < DD; ch += 256) {
        float a = w1*gap[ch];
        if (ch > 0)    a += w0*gap[ch-1];
        if (ch < DD-1) a += w2*gap[ch+1];
        att[ch] = 1.f/(1.f+expf(-a));
    }
    __syncthreads();

    int warp = tid >> 5, lane = tid & 31;
    float* gout = g_text + (size_t)b*FLAT;
    __half* sout = s_shift16 + (size_t)b*FLAT;
    for (int n = warp; n < NN; n += 8) {
        int base = n*DD;
        float buf[24];
        float s = 0.f;
        #pragma unroll
        for (int i = 0; i < 24; i++) {
            int d = i*32 + lane;
            int k = base + d;
            float x = src[k] * att[(unsigned)k/(unsigned)NN];
            gout[k] = x;
            float v = x + fcs[d];
            buf[i] = v;
            s += v;
        }
        #pragma unroll
        for (int o = 16; o; o >>= 1) s += __shfl_xor_sync(0xFFFFFFFFu, s, o);
        float mean = s * (1.f/DD);
        float q = 0.f;
        #pragma unroll
        for (int i = 0; i < 24; i++) { float z = buf[i]-mean; q += z*z; }
        #pragma unroll
        for (int o = 16; o; o >>= 1) q += __shfl_xor_sync(0xFFFFFFFFu, q, o);
        float rstd = rsqrtf(q*(1.f/DD) + 1e-5f);
        #pragma unroll
        for (int i = 0; i < 24; i++) {
            int d = i*32 + lane;
            sout[base + d] = __float2half_rn((buf[i]-mean)*rstd*ln_g[d] + ln_b[d]);
        }
    }
}

// ================= fp16 mma mainloop (generic): 2-stage cp.async + ldmatrix ========
__device__ __forceinline__ void mainloop_f16(
    const __half* __restrict__ Ab, const __half* __restrict__ Bb, int K,
    __half* Sh, float (&acc)[4][4][4])
{
    int tid  = threadIdx.x;
    int lane = tid & 31, warp = tid >> 5;
    int wm = (warp >> 2) * 64;
    int wn = (warp & 3) * 32;
    int ntiles = K >> 5;

    int part = lane >> 3, row8 = lane & 7;
    uint32_t offA[4], offB[2];
    #pragma unroll
    for (int mi = 0; mi < 4; mi++) {
        int r = wm + mi*16 + (part & 1)*8 + row8;
        offA[mi] = (uint32_t)(r*ROWH + (part >> 1)*8) * 2;
    }
    #pragma unroll
    for (int n2 = 0; n2 < 2; n2++) {
        int r = wn + n2*16 + (part >> 1)*8 + row8;
        offB[n2] = (uint32_t)(r*ROWH + (part & 1)*8) * 2;
    }
    uint32_t sbase = smem_u32(Sh);

    auto issue = [&](int kt, int s){
        __half* As = Sh + s*2*STAGE_H;
        __half* Bs = As + STAGE_H;
        #pragma unroll
        for (int i = 0; i < 2; i++) {
            int q = tid + i*256;
            int row = q >> 2, c = q & 3;
            uint32_t da = smem_u32(As + row*ROWH + c*8);
            uint32_t db = smem_u32(Bs + row*ROWH + c*8);
            const __half* ga = Ab + (size_t)row*K + kt*32 + c*8;
            const __half* gb = Bb + (size_t)row*K + kt*32 + c*8;
            asm volatile("cp.async.cg.shared.global [%0], [%1], 16;"
                         :: "r"(da), "l"(ga) : "memory");
            asm volatile("cp.async.cg.shared.global [%0], [%1], 16;"
                         :: "r"(db), "l"(gb) : "memory");
        }
        asm volatile("cp.async.commit_group;" ::: "memory");
    };

    issue(0, 0);
    for (int kt = 0; kt < ntiles; kt++) {
        if (kt + 1 < ntiles) {
            issue(kt + 1, (kt + 1) & 1);
            asm volatile("cp.async.wait_group 1;" ::: "memory");
        } else {
            asm volatile("cp.async.wait_group 0;" ::: "memory");
        }
        __syncthreads();

        uint32_t abase = sbase + (uint32_t)(kt & 1)*2*STAGE_H*2;
        uint32_t bbase = abase + STAGE_H*2;
        #pragma unroll
        for (int kk = 0; kk < 2; kk++) {
            uint32_t koff = kk * 32;
            uint32_t a[4][4], bfr[4][2];
            #pragma unroll
            for (int mi = 0; mi < 4; mi++)
                asm volatile("ldmatrix.sync.aligned.m8n8.x4.shared.b16 "
                    "{%0,%1,%2,%3}, [%4];"
                    : "=r"(a[mi][0]), "=r"(a[mi][1]), "=r"(a[mi][2]), "=r"(a[mi][3])
                    : "r"(abase + offA[mi] + koff));
            #pragma unroll
            for (int n2 = 0; n2 < 2; n2++)
                asm volatile("ldmatrix.sync.aligned.m8n8.x4.shared.b16 "
                    "{%0,%1,%2,%3}, [%4];"
                    : "=r"(bfr[2*n2][0]), "=r"(bfr[2*n2][1]),
                      "=r"(bfr[2*n2+1][0]), "=r"(bfr[2*n2+1][1])
                    : "r"(bbase + offB[n2] + koff));
            #pragma unroll
            for (int mi = 0; mi < 4; mi++)
                #pragma unroll
                for (int ni = 0; ni < 4; ni++)
                    asm volatile(
                      "mma.sync.aligned.m16n8k16.row.col.f32.f16.f16.f32 "
                      "{%0,%1,%2,%3}, {%4,%5,%6,%7}, {%8,%9}, {%0,%1,%2,%3};"
                      : "+f"(acc[mi][ni][0]), "+f"(acc[mi][ni][1]),
                        "+f"(acc[mi][ni][2]), "+f"(acc[mi][ni][3])
                      : "r"(a[mi][0]), "r"(a[mi][1]), "r"(a[mi][2]), "r"(a[mi][3]),
                        "r"(bfr[ni][0]), "r"(bfr[ni][1]));
        }
        __syncthreads();
    }
}

// ---------------- generic GEMM: C = (A@B^T + bias)*scale; fp32 or fp16 out ---------
__global__ __launch_bounds__(256,2) void gemm_f16(
    const __half* __restrict__ A, const __half* __restrict__ Bm,
    float* __restrict__ Cf, __half* __restrict__ Ch,
    int Nn, int K, const float* __restrict__ bias, float out_scale)
{
    __shared__ __align__(16) __half Sh[4*STAGE_H];
    float acc[4][4][4];
    #pragma unroll
    for (int i=0;i<4;i++) for (int j=0;j<4;j++) for (int r=0;r<4;r++) acc[i][j][r]=0.f;

    mainloop_f16(A + (size_t)blockIdx.y*128*K, Bm + (size_t)blockIdx.x*128*K, K, Sh, acc);

    int tid = threadIdx.x;
    int warp = tid >> 5, lane = tid & 31;
    int wm = (warp >> 2) * 64, wn = (warp & 3) * 32;
    int g = lane >> 2, cq = lane & 3;
    int row0 = blockIdx.y*128 + wm;
    int col0 = blockIdx.x*128 + wn;
    #pragma unroll
    for (int mi = 0; mi < 4; mi++)
        #pragma unroll
        for (int ni = 0; ni < 4; ni++) {
            int ra = row0 + mi*16 + g;
            int rb = ra + 8;
            int n0 = col0 + ni*8 + 2*cq;
            float v0 = (acc[mi][ni][0] + bias[n0])   * out_scale;
            float v1 = (acc[mi][ni][1] + bias[n0+1]) * out_scale;
            float v2 = (acc[mi][ni][2] + bias[n0])   * out_scale;
            float v3 = (acc[mi][ni][3] + bias[n0+1]) * out_scale;
            if (Ch) {
                *(__half2*)&Ch[(size_t)ra*Nn + n0] = __floats2half2_rn(v0, v1);
                *(__half2*)&Ch[(size_t)rb*Nn + n0] = __floats2half2_rn(v2, v3);
            } else {
                Cf[(size_t)ra*Nn + n0]   = v0;
                Cf[(size_t)ra*Nn + n0+1] = v1;
                Cf[(size_t)rb*Nn + n0]   = v2;
                Cf[(size_t)rb*Nn + n0+1] = v3;
            }
        }
}

// ---------------- LSTM step 0 (h=c=0): gates directly from xg ----------------
__global__ __launch_bounds__(256) void lstm_step0_kernel(float* __restrict__ out)
{
    int id = blockIdx.x*256 + threadIdx.x;   // < B*D
    int b = id / DD, jj = id - b*DD;
    uint2 raw = *reinterpret_cast<const uint2*>(&s_xg16[((size_t)b*NN)*D4 + 4*jj]);
    __half2 p0 = *(__half2*)&raw.x, p1 = *(__half2*)&raw.y;
    float gi = __low2float(p0), gg = __low2float(p1), go = __high2float(p1);
    float cn = fsig(gi) * ftanh(gg);
    s_c[id] = cn;
    float hn = fsig(go) * ftanh(cn);
    s_h16a[id] = __float2half_rn(hn);
    size_t oo = ((size_t)b*NN)*DD + jj;
    out[oo] = hn + g_text[oo];
}

// ---------------- persistent LSTM: 128 blocks (M128xN96), Whh resident -------------
// Barrier only among the 32 blocks sharing `by` (the only inter-step coupling is h).
__device__ __forceinline__ void group_sync(int grp)
{
    __syncthreads();
    if (threadIdx.x == 0) {
        __threadfence();
        int gen = *(volatile int*)&g_gen4[grp];
        if (atomicAdd(&g_cnt4[grp], 1) == GRPB-1) {
            g_cnt4[grp] = 0;
            __threadfence();
            *(volatile int*)&g_gen4[grp] = gen + 1;
        } else {
            while (*(volatile int*)&g_gen4[grp] == gen) __nanosleep(64);
        }
        __threadfence();
    }
    __syncthreads();
}

__global__ __launch_bounds__(256,1) void lstm_persistent(float* __restrict__ out)
{
    extern __shared__ __align__(16) __half S[];
    __half* Bres = S;                    // [96][PAD_B]
    __half* Ast  = S + PRS_BH;           // 3 A stages [128][ROWH]
    float*  ebuf = (float*)Ast;          // epilogue transpose 64x96 (after mainloop)
    int tid = threadIdx.x;
    int bx = blockIdx.x & 31;            // N tile (96 cols)
    int by = blockIdx.x >> 5;            // M tile (128 rows)

    // load resident B tile once: Whh16p rows [96*bx, +96), 768 cols
    {
        const __half* Bg = s_Whh16p + (size_t)bx*NT*DD;
        for (int i = tid; i < NT*(DD/8); i += 256) {
            int r = i / (DD/8), c8 = i - r*(DD/8);
            *reinterpret_cast<uint4*>(Bres + r*PAD_B + c8*8) =
                *reinterpret_cast<const uint4*>(Bg + (size_t)r*DD + c8*8);
        }
    }
    __syncthreads();

    int lane = tid & 31, warp = tid >> 5;
    int wm = (warp & 3) * 32;            // 4 M-splits of 32
    int wn = (warp >> 2) * 48;           // 2 N-splits of 48
    int part = lane >> 3, row8 = lane & 7;
    uint32_t offA[2], offB[3];
    #pragma unroll
    for (int mi = 0; mi < 2; mi++) {
        int r = wm + mi*16 + (part & 1)*8 + row8;
        offA[mi] = (uint32_t)(r*ROWH + (part >> 1)*8) * 2;
    }
    #pragma unroll
    for (int n4 = 0; n4 < 3; n4++) {
        int r = wn + n4*16 + (part >> 1)*8 + row8;
        offB[n4] = (uint32_t)(r*PAD_B + (part & 1)*8) * 2;
    }
    uint32_t sbA = smem_u32(Ast);
    uint32_t sbB = smem_u32(Bres);

    int g = lane >> 2, cq = lane & 3;

    for (int t = 1; t < NN; t++) {
        const __half* hin = (t & 1) ? s_h16a : s_h16b;
        __half* hout      = (t & 1) ? s_h16b : s_h16a;
        const __half* Ab = hin + (size_t)by*128*DD;

        auto issueA = [&](int kt, int s){
            #pragma unroll
            for (int i = 0; i < 2; i++) {
                int q = tid + i*256;
                int row = q >> 2, c = q & 3;
                uint32_t da = sbA + (uint32_t)(s*A_ST_H + row*ROWH + c*8)*2;
                const __half* ga = Ab + (size_t)row*DD + kt*32 + c*8;
                asm volatile("cp.async.cg.shared.global [%0], [%1], 16;"
                             :: "r"(da), "l"(ga) : "memory");
            }
            asm volatile("cp.async.commit_group;" ::: "memory");
        };

        float acc[2][6][4];
        #pragma unroll
        for (int i=0;i<2;i++) for (int j=0;j<6;j++) for (int r=0;r<4;r++) acc[i][j][r]=0.f;

        issueA(0, 0); issueA(1, 1);
        for (int kt = 0; kt < 24; kt++) {
            if (kt < 23) asm volatile("cp.async.wait_group 1;" ::: "memory");
            else         asm volatile("cp.async.wait_group 0;" ::: "memory");
            __syncthreads();
            if (kt + 2 < 24) issueA(kt + 2, (kt + 2) % 3);

            uint32_t abase = sbA + (uint32_t)((kt % 3)*A_ST_H)*2;
            uint32_t bcol  = (uint32_t)(kt*32)*2;
            #pragma unroll
            for (int kk = 0; kk < 2; kk++) {
                uint32_t koff = kk * 32;
                uint32_t a[2][4], bfr[6][2];
                #pragma unroll
                for (int mi = 0; mi < 2; mi++)
                    asm volatile("ldmatrix.sync.aligned.m8n8.x4.shared.b16 "
                        "{%0,%1,%2,%3}, [%4];"
                        : "=r"(a[mi][0]), "=r"(a[mi][1]), "=r"(a[mi][2]), "=r"(a[mi][3])
                        : "r"(abase + offA[mi] + koff));
                #pragma unroll
                for (int n4 = 0; n4 < 3; n4++)
                    asm volatile("ldmatrix.sync.aligned.m8n8.x4.shared.b16 "
                        "{%0,%1,%2,%3}, [%4];"
                        : "=r"(bfr[2*n4][0]), "=r"(bfr[2*n4][1]),
                          "=r"(bfr[2*n4+1][0]), "=r"(bfr[2*n4+1][1])
                        : "r"(sbB + offB[n4] + bcol + koff));
                #pragma unroll
                for (int mi = 0; mi < 2; mi++)
                    #pragma unroll
                    for (int ni = 0; ni < 6; ni++)
                        asm volatile(
                          "mma.sync.aligned.m16n8k16.row.col.f32.f16.f16.f32 "
                          "{%0,%1,%2,%3}, {%4,%5,%6,%7}, {%8,%9}, {%0,%1,%2,%3};"
                          : "+f"(acc[mi][ni][0]), "+f"(acc[mi][ni][1]),
                            "+f"(acc[mi][ni][2]), "+f"(acc[mi][ni][3])
                          : "r"(a[mi][0]), "r"(a[mi][1]), "r"(a[mi][2]), "r"(a[mi][3]),
                            "r"(bfr[ni][0]), "r"(bfr[ni][1]));
            }
            __syncthreads();
        }

        // epilogue: per 64-row half, transpose via ebuf then fused LSTM gates
        #pragma unroll
        for (int hf = 0; hf < 2; hf++) {
            __syncthreads();
            if (((warp & 3) >> 1) == hf) {
                int rbase = ((warp & 3) & 1)*32;
                #pragma unroll
                for (int mi = 0; mi < 2; mi++)
                    #pragma unroll
                    for (int ni = 0; ni < 6; ni++) {
                        int c0 = wn + ni*8 + 2*cq;
                        int r0 = rbase + mi*16 + g;
                        *reinterpret_cast<float2*>(&ebuf[r0*NT + (c0 ^ ((r0&7)<<2))]) =
                            make_float2(acc[mi][ni][0], acc[mi][ni][1]);
                        int r1 = r0 + 8;
                        *reinterpret_cast<float2*>(&ebuf[r1*NT + (c0 ^ ((r1&7)<<2))]) =
                            make_float2(acc[mi][ni][2], acc[mi][ni][3]);
                    }
            }
            __syncthreads();
            #pragma unroll
            for (int q = 0; q < 6; q++) {
                int idx = tid + q*256;          // < 1536
                int r = idx / 24, j = idx - r*24;
                int b = by*128 + hf*64 + r;
                int jjg = bx*24 + j;
                float4 acq = *reinterpret_cast<const float4*>(
                    &ebuf[r*NT + ((4*j) ^ ((r&7)<<2))]);
                uint2 raw = *reinterpret_cast<const uint2*>(
                    &s_xg16[((size_t)b*NN + t)*D4 + bx*NT + 4*j]);
                __half2 p0 = *(__half2*)&raw.x, p1 = *(__half2*)&raw.y;
                float gi = acq.x + __low2float(p0);
                float gf = acq.y + __high2float(p0);
                float gg = acq.z + __low2float(p1);
                float go = acq.w + __high2float(p1);
                int ci = b*DD + jjg;
                float c = s_c[ci];
                float cn = fsig(gf)*c + fsig(gi)*ftanh(gg);
                s_c[ci] = cn;
                float hn = fsig(go)*ftanh(cn);
                hout[ci] = __float2half_rn(hn);
                size_t oo = ((size_t)b*NN + t)*DD + jjg;
                out[oo] = hn + g_text[oo];
            }
        }
        group_sync(by);
    }
}

// ---------------- launch ----------------
extern "C" void kernel_launch(void* const* d_in, const int* in_sizes, int n_in,
                              void* d_out, int out_size)
{
    const float* text = (const float*)d_in[0];
    const int*   vids = (const int*)  d_in[1];
    const int*   aids = (const int*)  d_in[2];
    const float* vemb = (const float*)d_in[3];
    const float* aemb = (const float*)d_in[4];
    const float* w3   = (const float*)d_in[5];
    const float* Wih  = (const float*)d_in[6];
    const float* Whh  = (const float*)d_in[7];
    const float* bih  = (const float*)d_in[8];
    const float* bhh  = (const float*)d_in[9];
    const float* lng  = (const float*)d_in[10];
    const float* lnb  = (const float*)d_in[11];
    const float* vW   = (const float*)d_in[20];   // ca_vW [3,768,768]
    const float* vb   = (const float*)d_in[21];   // ca_vb [3,768]
    float* out = (float*)d_out;

    cudaFuncSetAttribute(lstm_persistent,
        cudaFuncAttributeMaxDynamicSharedMemorySize, PRS_SMEM);

    __half *p_vmam16, *p_shift16, *p_vWc16, *p_Wih16p, *p_xg16;
    float *p_fc, *p_vbsum, *p_bias_p;
    cudaGetSymbolAddress((void**)&p_vmam16, s_vmam16);
    cudaGetSymbolAddress((void**)&p_shift16, s_shift16);
    cudaGetSymbolAddress((void**)&p_vWc16, s_vWc16);
    cudaGetSymbolAddress((void**)&p_Wih16p, s_Wih16p);
    cudaGetSymbolAddress((void**)&p_xg16, s_xg16);
    cudaGetSymbolAddress((void**)&p_fc, s_fc);
    cudaGetSymbolAddress((void**)&p_vbsum, s_vbsum);
    cudaGetSymbolAddress((void**)&p_bias_p, s_bias_p);

    prep_kernel<<<(D4*DD + 255)/256, 256>>>(Wih, Whh, bih, bhh, vW, vb);
    egce_va<<<dim3(BB, 2), 256>>>(vids, aids, vemb, aemb, w3);

    // f_cross (K=1536): fc = ([vm|am] @ [vW0|W12]^T + vbsum) * (50/3)
    gemm_f16<<<dim3(DD/128, BB/128), 256>>>(
        p_vmam16, p_vWc16, p_fc, nullptr, DD, 2*DD, p_vbsum, 50.f/3.f);

    // fused egce(text) + fusion residual + LN
    egce_ln_kernel<<<BB, 256>>>(text, w3, lng, lnb);

    // xg (fp16) = shift @ Wih_perm^T + bias_perm   [25600, 3072]
    gemm_f16<<<dim3(D4/128, (BB*NN)/128), 256>>>(
        p_shift16, p_Wih16p, nullptr, p_xg16, D4, DD, p_bias_p, 1.f);

    // LSTM: t=0 from xg; t=1..49 inside one persistent kernel (128 blocks)
    lstm_step0_kernel<<<(BB*DD)/256, 256>>>(out);
    lstm_persistent<<<NBLK, 256, PRS_SMEM>>>(out);
}

// round 17
// speedup vs baseline: 1.1383x; 1.0188x over previous
#include <cuda_runtime.h>
#include <cuda_fp16.h>
#include <math.h>
#include <stdint.h>

#define BB 512
#define NN 50
#define DD 768
#define D4 3072
#define FLAT (NN*DD)   // 38400

#define ROWH 40                     // halves per A smem row (80B)
#define STAGE_H (128*ROWH)

// persistent LSTM: 128 blocks, tile M128 x N96, Whh N-tile resident
#define NT 96                       // N per block
#define NBLK 128                    // 4 * 32
#define GRPB 32                     // blocks per barrier group (same by)
#define PAD_B 776                   // halves per resident-B row
#define PRS_BH (NT*PAD_B)           // 74496 halves = 148992 B
#define A_ST_H (128*ROWH)           // 5120 halves per A stage
#define EBUF_B (128*NT*4)           // 49152 B separate epilogue buffer
#define PRS_SMEM (PRS_BH*2 + 3*A_ST_H*2 + EBUF_B)   // 228864 B

// ---------------- scratch (__device__ globals; no allocation allowed) ----------------
__device__ float  g_text[BB*FLAT];
__device__ __align__(16) __half s_shift16[BB*FLAT];
__device__ __align__(16) __half s_xg16[(size_t)BB*NN*D4];   // permuted gate pre-acts
__device__ __align__(16) __half s_h16a[BB*DD];
__device__ __align__(16) __half s_h16b[BB*DD];
__device__ float  s_c  [BB*DD];
__device__ __align__(16) __half s_vmam16[BB*2*DD];          // [b][vm|am]
__device__ float  s_fc [BB*DD];
__device__ __align__(16) __half s_Wih16p[(size_t)D4*DD];    // gate-interleaved rows
__device__ __align__(16) __half s_Whh16p[(size_t)D4*DD];
__device__ __align__(16) __half s_vWc16 [(size_t)DD*2*DD];  // [n][vW0|vW1+vW2]
__device__ float  s_bias_p[D4];
__device__ float  s_vbsum[DD];
__device__ int    g_cnt4[4];
__device__ int    g_gen4[4];

__device__ __forceinline__ float fsig(float x){
    return __fdividef(1.f, 1.f + __expf(-x));
}
__device__ __forceinline__ float ftanh(float x){
    return __fdividef(2.f, 1.f + __expf(-2.f*x)) - 1.f;
}
__device__ __forceinline__ uint32_t smem_u32(const void* p){
    uint32_t a;
    asm("{ .reg .u64 t; cvta.to.shared.u64 t, %1; cvt.u32.u64 %0, t; }"
        : "=r"(a) : "l"(p));
    return a;
}

// ---------------- prep: convert weights to fp16 (permuted), combine biases ----------
__global__ __launch_bounds__(256) void prep_kernel(
    const float* __restrict__ Wih, const float* __restrict__ Whh,
    const float* __restrict__ bih, const float* __restrict__ bhh,
    const float* __restrict__ vW,  const float* __restrict__ vb)
{
    int i = blockIdx.x*256 + threadIdx.x;
    if (i < D4*DD) {
        int p = i / DD, k = i - p*DD;
        int orig = (p & 3)*DD + (p >> 2);          // gate-interleave: p = 4*jj + gate
        s_Wih16p[i] = __float2half_rn(Wih[(size_t)orig*DD + k]);
        s_Whh16p[i] = __float2half_rn(Whh[(size_t)orig*DD + k]);
    }
    if (i < D4) {
        int orig = (i & 3)*DD + (i >> 2);
        s_bias_p[i] = bih[orig] + bhh[orig];
    }
    if (i < DD*DD) {
        int n = i / DD, k = i - n*DD;
        s_vWc16[(size_t)n*2*DD + k]      = __float2half_rn(vW[i]);
        s_vWc16[(size_t)n*2*DD + DD + k] =
            __float2half_rn(vW[DD*DD + i] + vW[2*DD*DD + i]);
    }
    if (i < DD) s_vbsum[i] = vb[i] + vb[DD+i] + vb[2*DD+i];
    if (i < 4) { g_cnt4[i] = 0; g_gen4[i] = 0; }
}

// ---------------- EGCE visual/acoustic: gated means straight from tables -----------
__global__ __launch_bounds__(256) void egce_va(
    const int* __restrict__ vids, const int* __restrict__ aids,
    const float* __restrict__ vemb, const float* __restrict__ aemb,
    const float* __restrict__ w3)
{
    int b = blockIdx.x;
    int mode = blockIdx.y;        // 0=visual(relu), 1=acoustic
    int tid = threadIdx.x;
    __shared__ int ids[NN];
    __shared__ float gap[DD], att[DD];
    if (tid < NN)
        ids[tid] = mode ? aids[b*NN+tid] : vids[b*NN+tid];
    __syncthreads();
    const float* emb = mode ? aemb : vemb;

    for (int ch = tid; ch < DD; ch += 256) {
        float s = 0.f; int base = ch*NN;
        for (int j = 0; j < NN; j++) {
            int k = base + j;
            int n = k / DD, d = k - n*DD;
            float v = emb[(size_t)ids[n]*DD + d];
            if (!mode) v = fmaxf(v, 0.f);
            s += v;
        }
        gap[ch] = s * (1.f/NN);
    }
    __syncthreads();
    float w0 = w3[0], w1 = w3[1], w2 = w3[2];
    for (int ch = tid; ch < DD; ch += 256) {
        float a = w1*gap[ch];
        if (ch > 0)    a += w0*gap[ch-1];
        if (ch < DD-1) a += w2*gap[ch+1];
        att[ch] = 1.f/(1.f+expf(-a));
    }
    __syncthreads();
    for (int d = tid; d < DD; d += 256) {
        float acc = 0.f;
        for (int n = 0; n < NN; n++) {
            float v = emb[(size_t)ids[n]*DD + d];
            if (!mode) v = fmaxf(v, 0.f);
            acc += v * att[(n*DD + d)/NN];
        }
        s_vmam16[(size_t)b*2*DD + mode*DD + d] = __float2half_rn(acc * (1.f/NN));
    }
}

// -------- fused EGCE(text) + f_cross-residual + LayerNorm -> g_text, shift16 -------
__global__ __launch_bounds__(256) void egce_ln_kernel(
    const float* __restrict__ text, const float* __restrict__ w3,
    const float* __restrict__ ln_g, const float* __restrict__ ln_b)
{
    int b = blockIdx.x, tid = threadIdx.x;
    __shared__ float gap[DD], att[DD], fcs[DD];
    const float* src = text + (size_t)b*FLAT;

    for (int ch = tid; ch < DD; ch += 256) {
        float s = 0.f; int base = ch*NN;
        #pragma unroll 5
        for (int j = 0; j < NN; j++) s += src[base+j];
        gap[ch] = s * (1.f/NN);
        fcs[ch] = s_fc[(size_t)b*DD + ch];
    }
    __syncthreads();
    float w0 = w3[0], w1 = w3[1], w2 = w3[2];
    for (int ch = tid; ch < DD; ch += 256) {
        float a = w1*gap[ch];
        if (ch > 0)    a += w0*gap[ch-1];
        if (ch < DD-1) a += w2*gap[ch+1];
        att[ch] = 1.f/(1.f+expf(-a));
    }
    __syncthreads();

    int warp = tid >> 5, lane = tid & 31;
    float* gout = g_text + (size_t)b*FLAT;
    __half* sout = s_shift16 + (size_t)b*FLAT;
    for (int n = warp; n < NN; n += 8) {
        int base = n*DD;
        float buf[24];
        float s = 0.f;
        #pragma unroll
        for (int i = 0; i < 24; i++) {
            int d = i*32 + lane;
            int k = base + d;
            float x = src[k] * att[(unsigned)k/(unsigned)NN];
            gout[k] = x;
            float v = x + fcs[d];
            buf[i] = v;
            s += v;
        }
        #pragma unroll
        for (int o = 16; o; o >>= 1) s += __shfl_xor_sync(0xFFFFFFFFu, s, o);
        float mean = s * (1.f/DD);
        float q = 0.f;
        #pragma unroll
        for (int i = 0; i < 24; i++) { float z = buf[i]-mean; q += z*z; }
        #pragma unroll
        for (int o = 16; o; o >>= 1) q += __shfl_xor_sync(0xFFFFFFFFu, q, o);
        float rstd = rsqrtf(q*(1.f/DD) + 1e-5f);
        #pragma unroll
        for (int i = 0; i < 24; i++) {
            int d = i*32 + lane;
            sout[base + d] = __float2half_rn((buf[i]-mean)*rstd*ln_g[d] + ln_b[d]);
        }
    }
}

// ================= fp16 mma mainloop (generic): 2-stage cp.async + ldmatrix ========
__device__ __forceinline__ void mainloop_f16(
    const __half* __restrict__ Ab, const __half* __restrict__ Bb, int K,
    __half* Sh, float (&acc)[4][4][4])
{
    int tid  = threadIdx.x;
    int lane = tid & 31, warp = tid >> 5;
    int wm = (warp >> 2) * 64;
    int wn = (warp & 3) * 32;
    int ntiles = K >> 5;

    int part = lane >> 3, row8 = lane & 7;
    uint32_t offA[4], offB[2];
    #pragma unroll
    for (int mi = 0; mi < 4; mi++) {
        int r = wm + mi*16 + (part & 1)*8 + row8;
        offA[mi] = (uint32_t)(r*ROWH + (part >> 1)*8) * 2;
    }
    #pragma unroll
    for (int n2 = 0; n2 < 2; n2++) {
        int r = wn + n2*16 + (part >> 1)*8 + row8;
        offB[n2] = (uint32_t)(r*ROWH + (part & 1)*8) * 2;
    }
    uint32_t sbase = smem_u32(Sh);

    auto issue = [&](int kt, int s){
        __half* As = Sh + s*2*STAGE_H;
        __half* Bs = As + STAGE_H;
        #pragma unroll
        for (int i = 0; i < 2; i++) {
            int q = tid + i*256;
            int row = q >> 2, c = q & 3;
            uint32_t da = smem_u32(As + row*ROWH + c*8);
            uint32_t db = smem_u32(Bs + row*ROWH + c*8);
            const __half* ga = Ab + (size_t)row*K + kt*32 + c*8;
            const __half* gb = Bb + (size_t)row*K + kt*32 + c*8;
            asm volatile("cp.async.cg.shared.global [%0], [%1], 16;"
                         :: "r"(da), "l"(ga) : "memory");
            asm volatile("cp.async.cg.shared.global [%0], [%1], 16;"
                         :: "r"(db), "l"(gb) : "memory");
        }
        asm volatile("cp.async.commit_group;" ::: "memory");
    };

    issue(0, 0);
    for (int kt = 0; kt < ntiles; kt++) {
        if (kt + 1 < ntiles) {
            issue(kt + 1, (kt + 1) & 1);
            asm volatile("cp.async.wait_group 1;" ::: "memory");
        } else {
            asm volatile("cp.async.wait_group 0;" ::: "memory");
        }
        __syncthreads();

        uint32_t abase = sbase + (uint32_t)(kt & 1)*2*STAGE_H*2;
        uint32_t bbase = abase + STAGE_H*2;
        #pragma unroll
        for (int kk = 0; kk < 2; kk++) {
            uint32_t koff = kk * 32;
            uint32_t a[4][4], bfr[4][2];
            #pragma unroll
            for (int mi = 0; mi < 4; mi++)
                asm volatile("ldmatrix.sync.aligned.m8n8.x4.shared.b16 "
                    "{%0,%1,%2,%3}, [%4];"
                    : "=r"(a[mi][0]), "=r"(a[mi][1]), "=r"(a[mi][2]), "=r"(a[mi][3])
                    : "r"(abase + offA[mi] + koff));
            #pragma unroll
            for (int n2 = 0; n2 < 2; n2++)
                asm volatile("ldmatrix.sync.aligned.m8n8.x4.shared.b16 "
                    "{%0,%1,%2,%3}, [%4];"
                    : "=r"(bfr[2*n2][0]), "=r"(bfr[2*n2][1]),
                      "=r"(bfr[2*n2+1][0]), "=r"(bfr[2*n2+1][1])
                    : "r"(bbase + offB[n2] + koff));
            #pragma unroll
            for (int mi = 0; mi < 4; mi++)
                #pragma unroll
                for (int ni = 0; ni < 4; ni++)
                    asm volatile(
                      "mma.sync.aligned.m16n8k16.row.col.f32.f16.f16.f32 "
                      "{%0,%1,%2,%3}, {%4,%5,%6,%7}, {%8,%9}, {%0,%1,%2,%3};"
                      : "+f"(acc[mi][ni][0]), "+f"(acc[mi][ni][1]),
                        "+f"(acc[mi][ni][2]), "+f"(acc[mi][ni][3])
                      : "r"(a[mi][0]), "r"(a[mi][1]), "r"(a[mi][2]), "r"(a[mi][3]),
                        "r"(bfr[ni][0]), "r"(bfr[ni][1]));
        }
        __syncthreads();
    }
}

// ---------------- generic GEMM: C = (A@B^T + bias)*scale; fp32 or fp16 out ---------
__global__ __launch_bounds__(256,2) void gemm_f16(
    const __half* __restrict__ A, const __half* __restrict__ Bm,
    float* __restrict__ Cf, __half* __restrict__ Ch,
    int Nn, int K, const float* __restrict__ bias, float out_scale)
{
    __shared__ __align__(16) __half Sh[4*STAGE_H];
    float acc[4][4][4];
    #pragma unroll
    for (int i=0;i<4;i++) for (int j=0;j<4;j++) for (int r=0;r<4;r++) acc[i][j][r]=0.f;

    mainloop_f16(A + (size_t)blockIdx.y*128*K, Bm + (size_t)blockIdx.x*128*K, K, Sh, acc);

    int tid = threadIdx.x;
    int warp = tid >> 5, lane = tid & 31;
    int wm = (warp >> 2) * 64, wn = (warp & 3) * 32;
    int g = lane >> 2, cq = lane & 3;
    int row0 = blockIdx.y*128 + wm;
    int col0 = blockIdx.x*128 + wn;
    #pragma unroll
    for (int mi = 0; mi < 4; mi++)
        #pragma unroll
        for (int ni = 0; ni < 4; ni++) {
            int ra = row0 + mi*16 + g;
            int rb = ra + 8;
            int n0 = col0 + ni*8 + 2*cq;
            float v0 = (acc[mi][ni][0] + bias[n0])   * out_scale;
            float v1 = (acc[mi][ni][1] + bias[n0+1]) * out_scale;
            float v2 = (acc[mi][ni][2] + bias[n0])   * out_scale;
            float v3 = (acc[mi][ni][3] + bias[n0+1]) * out_scale;
            if (Ch) {
                *(__half2*)&Ch[(size_t)ra*Nn + n0] = __floats2half2_rn(v0, v1);
                *(__half2*)&Ch[(size_t)rb*Nn + n0] = __floats2half2_rn(v2, v3);
            } else {
                Cf[(size_t)ra*Nn + n0]   = v0;
                Cf[(size_t)ra*Nn + n0+1] = v1;
                Cf[(size_t)rb*Nn + n0]   = v2;
                Cf[(size_t)rb*Nn + n0+1] = v3;
            }
        }
}

// ---------------- LSTM step 0 (h=c=0): gates directly from xg ----------------
__global__ __launch_bounds__(256) void lstm_step0_kernel(float* __restrict__ out)
{
    int id = blockIdx.x*256 + threadIdx.x;   // < B*D
    int b = id / DD, jj = id - b*DD;
    uint2 raw = *reinterpret_cast<const uint2*>(&s_xg16[((size_t)b*NN)*D4 + 4*jj]);
    __half2 p0 = *(__half2*)&raw.x, p1 = *(__half2*)&raw.y;
    float gi = __low2float(p0), gg = __low2float(p1), go = __high2float(p1);
    float cn = fsig(gi) * ftanh(gg);
    s_c[id] = cn;
    float hn = fsig(go) * ftanh(cn);
    s_h16a[id] = __float2half_rn(hn);
    size_t oo = ((size_t)b*NN)*DD + jj;
    out[oo] = hn + g_text[oo];
}

// ---------------- persistent LSTM: 128 blocks (M128xN96), Whh resident -------------
// Barrier only among the 32 blocks sharing `by` (the only inter-step coupling is h).
__device__ __forceinline__ void group_sync(int grp)
{
    __syncthreads();
    if (threadIdx.x == 0) {
        __threadfence();
        int gen = *(volatile int*)&g_gen4[grp];
        if (atomicAdd(&g_cnt4[grp], 1) == GRPB-1) {
            g_cnt4[grp] = 0;
            __threadfence();
            *(volatile int*)&g_gen4[grp] = gen + 1;
        } else {
            while (*(volatile int*)&g_gen4[grp] == gen) __nanosleep(64);
        }
        __threadfence();
    }
    __syncthreads();
}

__global__ __launch_bounds__(256,1) void lstm_persistent(float* __restrict__ out)
{
    extern __shared__ __align__(16) __half S[];
    __half* Bres = S;                          // [96][PAD_B]
    __half* Ast  = S + PRS_BH;                 // 3 A stages [128][ROWH]
    float*  ebuf = (float*)(S + PRS_BH + 3*A_ST_H);  // separate 128x96 epilogue buf
    int tid = threadIdx.x;
    int bx = blockIdx.x & 31;            // N tile (96 cols)
    int by = blockIdx.x >> 5;            // M tile (128 rows)

    // load resident B tile once: Whh16p rows [96*bx, +96), 768 cols
    {
        const __half* Bg = s_Whh16p + (size_t)bx*NT*DD;
        for (int i = tid; i < NT*(DD/8); i += 256) {
            int r = i / (DD/8), c8 = i - r*(DD/8);
            *reinterpret_cast<uint4*>(Bres + r*PAD_B + c8*8) =
                *reinterpret_cast<const uint4*>(Bg + (size_t)r*DD + c8*8);
        }
    }
    __syncthreads();

    int lane = tid & 31, warp = tid >> 5;
    int wm = (warp & 3) * 32;            // 4 M-splits of 32
    int wn = (warp >> 2) * 48;           // 2 N-splits of 48
    int part = lane >> 3, row8 = lane & 7;
    uint32_t offA[2], offB[3];
    #pragma unroll
    for (int mi = 0; mi < 2; mi++) {
        int r = wm + mi*16 + (part & 1)*8 + row8;
        offA[mi] = (uint32_t)(r*ROWH + (part >> 1)*8) * 2;
    }
    #pragma unroll
    for (int n4 = 0; n4 < 3; n4++) {
        int r = wn + n4*16 + (part >> 1)*8 + row8;
        offB[n4] = (uint32_t)(r*PAD_B + (part & 1)*8) * 2;
    }
    uint32_t sbA = smem_u32(Ast);
    uint32_t sbB = smem_u32(Bres);

    int g = lane >> 2, cq = lane & 3;

    for (int t = 1; t < NN; t++) {
        const __half* hin = (t & 1) ? s_h16a : s_h16b;
        __half* hout      = (t & 1) ? s_h16b : s_h16a;
        const __half* Ab = hin + (size_t)by*128*DD;

        auto issueA = [&](int kt, int s){
            #pragma unroll
            for (int i = 0; i < 2; i++) {
                int q = tid + i*256;
                int row = q >> 2, c = q & 3;
                uint32_t da = sbA + (uint32_t)(s*A_ST_H + row*ROWH + c*8)*2;
                const __half* ga = Ab + (size_t)row*DD + kt*32 + c*8;
                asm volatile("cp.async.cg.shared.global [%0], [%1], 16;"
                             :: "r"(da), "l"(ga) : "memory");
            }
            asm volatile("cp.async.commit_group;" ::: "memory");
        };

        float acc[2][6][4];
        #pragma unroll
        for (int i=0;i<2;i++) for (int j=0;j<6;j++) for (int r=0;r<4;r++) acc[i][j][r]=0.f;

        issueA(0, 0); issueA(1, 1);
        for (int kt = 0; kt < 24; kt++) {
            if (kt < 23) asm volatile("cp.async.wait_group 1;" ::: "memory");
            else         asm volatile("cp.async.wait_group 0;" ::: "memory");
            __syncthreads();
            if (kt + 2 < 24) issueA(kt + 2, (kt + 2) % 3);

            uint32_t abase = sbA + (uint32_t)((kt % 3)*A_ST_H)*2;
            uint32_t bcol  = (uint32_t)(kt*32)*2;
            #pragma unroll
            for (int kk = 0; kk < 2; kk++) {
                uint32_t koff = kk * 32;
                uint32_t a[2][4], bfr[6][2];
                #pragma unroll
                for (int mi = 0; mi < 2; mi++)
                    asm volatile("ldmatrix.sync.aligned.m8n8.x4.shared.b16 "
                        "{%0,%1,%2,%3}, [%4];"
                        : "=r"(a[mi][0]), "=r"(a[mi][1]), "=r"(a[mi][2]), "=r"(a[mi][3])
                        : "r"(abase + offA[mi] + koff));
                #pragma unroll
                for (int n4 = 0; n4 < 3; n4++)
                    asm volatile("ldmatrix.sync.aligned.m8n8.x4.shared.b16 "
                        "{%0,%1,%2,%3}, [%4];"
                        : "=r"(bfr[2*n4][0]), "=r"(bfr[2*n4][1]),
                          "=r"(bfr[2*n4+1][0]), "=r"(bfr[2*n4+1][1])
                        : "r"(sbB + offB[n4] + bcol + koff));
                #pragma unroll
                for (int mi = 0; mi < 2; mi++)
                    #pragma unroll
                    for (int ni = 0; ni < 6; ni++)
                        asm volatile(
                          "mma.sync.aligned.m16n8k16.row.col.f32.f16.f16.f32 "
                          "{%0,%1,%2,%3}, {%4,%5,%6,%7}, {%8,%9}, {%0,%1,%2,%3};"
                          : "+f"(acc[mi][ni][0]), "+f"(acc[mi][ni][1]),
                            "+f"(acc[mi][ni][2]), "+f"(acc[mi][ni][3])
                          : "r"(a[mi][0]), "r"(a[mi][1]), "r"(a[mi][2]), "r"(a[mi][3]),
                            "r"(bfr[ni][0]), "r"(bfr[ni][1]));
            }
            __syncthreads();
        }

        // single-shot epilogue: all warps dump acc to dedicated ebuf, one sync
        #pragma unroll
        for (int mi = 0; mi < 2; mi++)
            #pragma unroll
            for (int ni = 0; ni < 6; ni++) {
                int c0 = wn + ni*8 + 2*cq;
                int r0 = wm + mi*16 + g;
                *reinterpret_cast<float2*>(&ebuf[r0*NT + (c0 ^ ((r0&7)<<2))]) =
                    make_float2(acc[mi][ni][0], acc[mi][ni][1]);
                int r1 = r0 + 8;
                *reinterpret_cast<float2*>(&ebuf[r1*NT + (c0 ^ ((r1&7)<<2))]) =
                    make_float2(acc[mi][ni][2], acc[mi][ni][3]);
            }
        __syncthreads();
        #pragma unroll
        for (int q = 0; q < 12; q++) {
            int idx = tid + q*256;          // < 3072 = 128 rows * 24 units
            int r = idx / 24, j = idx - r*24;
            int b = by*128 + r;
            int jjg = bx*24 + j;
            float4 acq = *reinterpret_cast<const float4*>(
                &ebuf[r*NT + ((4*j) ^ ((r&7)<<2))]);
            uint2 raw = *reinterpret_cast<const uint2*>(
                &s_xg16[((size_t)b*NN + t)*D4 + bx*NT + 4*j]);
            __half2 p0 = *(__half2*)&raw.x, p1 = *(__half2*)&raw.y;
            float gi = acq.x + __low2float(p0);
            float gf = acq.y + __high2float(p0);
            float gg = acq.z + __low2float(p1);
            float go = acq.w + __high2float(p1);
            int ci = b*DD + jjg;
            float c = s_c[ci];
            float cn = fsig(gf)*c + fsig(gi)*ftanh(gg);
            s_c[ci] = cn;
            float hn = fsig(go)*ftanh(cn);
            hout[ci] = __float2half_rn(hn);
            size_t oo = ((size_t)b*NN + t)*DD + jjg;
            out[oo] = hn + g_text[oo];
        }
        group_sync(by);
    }
}

// ---------------- launch ----------------
extern "C" void kernel_launch(void* const* d_in, const int* in_sizes, int n_in,
                              void* d_out, int out_size)
{
    const float* text = (const float*)d_in[0];
    const int*   vids = (const int*)  d_in[1];
    const int*   aids = (const int*)  d_in[2];
    const float* vemb = (const float*)d_in[3];
    const float* aemb = (const float*)d_in[4];
    const float* w3   = (const float*)d_in[5];
    const float* Wih  = (const float*)d_in[6];
    const float* Whh  = (const float*)d_in[7];
    const float* bih  = (const float*)d_in[8];
    const float* bhh  = (const float*)d_in[9];
    const float* lng  = (const float*)d_in[10];
    const float* lnb  = (const float*)d_in[11];
    const float* vW   = (const float*)d_in[20];   // ca_vW [3,768,768]
    const float* vb   = (const float*)d_in[21];   // ca_vb [3,768]
    float* out = (float*)d_out;

    cudaFuncSetAttribute(lstm_persistent,
        cudaFuncAttributeMaxDynamicSharedMemorySize, PRS_SMEM);

    __half *p_vmam16, *p_shift16, *p_vWc16, *p_Wih16p, *p_xg16;
    float *p_fc, *p_vbsum, *p_bias_p;
    cudaGetSymbolAddress((void**)&p_vmam16, s_vmam16);
    cudaGetSymbolAddress((void**)&p_shift16, s_shift16);
    cudaGetSymbolAddress((void**)&p_vWc16, s_vWc16);
    cudaGetSymbolAddress((void**)&p_Wih16p, s_Wih16p);
    cudaGetSymbolAddress((void**)&p_xg16, s_xg16);
    cudaGetSymbolAddress((void**)&p_fc, s_fc);
    cudaGetSymbolAddress((void**)&p_vbsum, s_vbsum);
    cudaGetSymbolAddress((void**)&p_bias_p, s_bias_p);

    prep_kernel<<<(D4*DD + 255)/256, 256>>>(Wih, Whh, bih, bhh, vW, vb);
    egce_va<<<dim3(BB, 2), 256>>>(vids, aids, vemb, aemb, w3);

    // f_cross (K=1536): fc = ([vm|am] @ [vW0|W12]^T + vbsum) * (50/3)
    gemm_f16<<<dim3(DD/128, BB/128), 256>>>(
        p_vmam16, p_vWc16, p_fc, nullptr, DD, 2*DD, p_vbsum, 50.f/3.f);

    // fused egce(text) + fusion residual + LN
    egce_ln_kernel<<<BB, 256>>>(text, w3, lng, lnb);

    // xg (fp16) = shift @ Wih_perm^T + bias_perm   [25600, 3072]
    gemm_f16<<<dim3(D4/128, (BB*NN)/128), 256>>>(
        p_shift16, p_Wih16p, nullptr, p_xg16, D4, DD, p_bias_p, 1.f);

    // LSTM: t=0 from xg; t=1..49 inside one persistent kernel (128 blocks)
    lstm_step0_kernel<<<(BB*DD)/256, 256>>>(out);
    lstm_persistent<<<NBLK, 256, PRS_SMEM>>>(out);
}